// round 1
// baseline (speedup 1.0000x reference)
#include <cuda_runtime.h>
#include <math.h>

#define NMAX     12288
#define QB       128
#define SPLITS   8
#define TILE_MAX 1536   // NMAX rounded to 256 is 12288; 12288/8 = 1536

struct CMat { float m[9]; float s; };

// ---- scratch (no allocations allowed) ----
__device__ float4 g_cand[NMAX + 256];           // compacted inside points: {x,y,z, |w|^2}; padded with BIG
__device__ int    g_cidx[NMAX];                 // compacted -> original index
__device__ int    g_count[2];                   // [0]=Nc, [1]=Ncp (padded to 256)
__device__ float  g_pval[SPLITS * NMAX];        // partial min values per split
__device__ int    g_pidx[SPLITS * NMAX];        // partial argmin (compact index)
__device__ double g_blk_sum[64];
__device__ int    g_blk_cnt[64];

// ============================================================
// Kernel 1: deterministic compaction of inside points (1 block)
// ============================================================
__global__ void k_compact(const float* __restrict__ new_xyz,
                          const float* __restrict__ gt_sdf, int n) {
    __shared__ int s_wsum[32];
    __shared__ int s_base;
    int tid  = threadIdx.x;            // 1024 threads
    int lane = tid & 31, wid = tid >> 5;
    if (tid == 0) s_base = 0;
    __syncthreads();

    for (int chunk = 0; chunk < n; chunk += 1024) {
        int idx = chunk + tid;
        bool f = (idx < n) && (gt_sdf[idx] < 1e-8f);
        unsigned bal = __ballot_sync(0xffffffffu, f);
        int wcnt = __popc(bal);
        int pre  = __popc(bal & ((1u << lane) - 1u));
        if (lane == 0) s_wsum[wid] = wcnt;
        __syncthreads();
        int base = s_base;
        int woff = 0, tot = 0;
        #pragma unroll
        for (int wv = 0; wv < 32; ++wv) {
            int v = s_wsum[wv];
            tot += v;
            if (wv < wid) woff += v;
        }
        if (f) {
            int pos = base + woff + pre;
            float x = new_xyz[3 * idx + 0];
            float y = new_xyz[3 * idx + 1];
            float z = new_xyz[3 * idx + 2];
            g_cidx[pos] = idx;
            g_cand[pos] = make_float4(x, y, z, x * x + y * y + z * z);
        }
        __syncthreads();
        if (tid == 0) s_base = base + tot;
        __syncthreads();
    }

    int Nc  = s_base;
    int Ncp = (Nc + 255) & ~255;
    for (int p = Nc + tid; p < Ncp; p += 1024)
        g_cand[p] = make_float4(0.f, 0.f, 0.f, 1e30f);   // padding never wins the min
    if (tid == 0) { g_count[0] = Nc; g_count[1] = Ncp; }
}

// ============================================================
// Kernel 2: NN search (split-j). grid = (ceil(n/QB), SPLITS)
// d_eff = sq_j - 2 w_i . w_j  (query constant sq_i dropped)
// ============================================================
__global__ void __launch_bounds__(QB) k_nn() {
    __shared__ float4 tile[TILE_MAX];
    int Nc  = g_count[0];
    int Ncp = g_count[1];
    int qb  = blockIdx.x;
    int sp  = blockIdx.y;
    int qi  = qb * QB + threadIdx.x;
    if (qb * QB >= Nc) return;                 // whole block idle (uniform)

    int Lp = Ncp / SPLITS;                     // Ncp multiple of 256 -> exact
    int c0 = sp * Lp;
    int c1 = c0 + Lp;
    for (int k = threadIdx.x; k < Lp; k += QB) tile[k] = g_cand[c0 + k];
    __syncthreads();

    float4 wq = g_cand[min(qi, Ncp - 1)];
    float ax = -2.f * wq.x, ay = -2.f * wq.y, az = -2.f * wq.z;
    float best = 3.0e38f;
    int   bc   = 0;

    // block-uniform choice: only blocks whose query range overlaps this split
    // need the self-exclusion check
    bool slow = (qb * QB < c1) && (qb * QB + QB > c0);
    if (!slow) {
        #pragma unroll 8
        for (int k = 0; k < Lp; ++k) {
            float4 c = tile[k];
            float d = fmaf(c.x, ax, fmaf(c.y, ay, fmaf(c.z, az, c.w)));
            if (d < best) { best = d; bc = k; }
        }
    } else {
        int sk = qi - c0;   // out of [0,Lp) for threads whose self isn't here -> harmless
        #pragma unroll 8
        for (int k = 0; k < Lp; ++k) {
            float4 c = tile[k];
            float d = fmaf(c.x, ax, fmaf(c.y, ay, fmaf(c.z, az, c.w)));
            if (d < best && k != sk) { best = d; bc = k; }
        }
    }

    if (qi < Nc) {
        g_pval[sp * NMAX + qi] = best;
        g_pidx[sp * NMAX + qi] = bc + c0;
    }
}

// ============================================================
// Kernel 3: combine splits + strain + per-block reduction
// ============================================================
__global__ void k_strain(const float* __restrict__ new_xyz,
                         const float* __restrict__ xyz, CMat C) {
    __shared__ double s_sum[256];
    __shared__ int    s_cnt[256];
    int Nc = g_count[0];
    int t  = threadIdx.x;
    int qi = blockIdx.x * 256 + t;

    double qsq = 0.0;
    int cnt = 0;
    if (qi < Nc) {
        float best = 3.5e38f;
        int bc = 0;
        #pragma unroll
        for (int s = 0; s < SPLITS; ++s) {      // ascending: first-occurrence tiebreak
            float v = g_pval[s * NMAX + qi];
            int id  = g_pidx[s * NMAX + qi];
            if (v < best) { best = v; bc = id; }
        }
        float4 wq = g_cand[qi];
        float mind2 = best + wq.w;              // add back sq_i
        if (mind2 > 1e-16f) {                   // == (sqrt(max(d2,0)) > 1e-8) & inside
            cnt = 1;
            int i  = g_cidx[qi];
            int nn = g_cidx[bc];
            float4 wn = g_cand[bc];
            float xi0 = xyz[3 * i + 0],  xi1 = xyz[3 * i + 1],  xi2 = xyz[3 * i + 2];
            float xn0 = xyz[3 * nn + 0], xn1 = xyz[3 * nn + 1], xn2 = xyz[3 * nn + 2];
            // dm = motion[nn] - motion[i], same rounding order as reference
            float du = (wn.x - xn0) - (wq.x - xi0);
            float dv = (wn.y - xn1) - (wq.y - xi1);
            float dw = (wn.z - xn2) - (wq.z - xi2);
            float dx = wn.x - wq.x + 1e-8f;
            float dy = wn.y - wq.y + 1e-8f;
            float dz = wn.z - wq.z + 1e-8f;
            float e0 = du / dx, e1 = dv / dy, e2 = dw / dz;
            float e3 = (du / dy + dv / dx) * 0.5f;
            float e4 = (du / dz + dw / dx) * 0.5f;
            float e5 = (dw / dy + dv / dz) * 0.5f;
            float r0 = C.m[0] * e0 + C.m[1] * e1 + C.m[2] * e2;
            float r1 = C.m[3] * e0 + C.m[4] * e1 + C.m[5] * e2;
            float r2 = C.m[6] * e0 + C.m[7] * e1 + C.m[8] * e2;
            float q  = e0 * r0 + e1 * r1 + e2 * r2
                     + C.s * (e3 * e3 + e4 * e4 + e5 * e5);
            qsq = (double)q * (double)q;
        }
    }
    s_sum[t] = qsq;
    s_cnt[t] = cnt;
    __syncthreads();
    #pragma unroll
    for (int o = 128; o > 0; o >>= 1) {         // deterministic tree
        if (t < o) { s_sum[t] += s_sum[t + o]; s_cnt[t] += s_cnt[t + o]; }
        __syncthreads();
    }
    if (t == 0) { g_blk_sum[blockIdx.x] = s_sum[0]; g_blk_cnt[blockIdx.x] = s_cnt[0]; }
}

// ============================================================
// Kernel 4: final scalar
// ============================================================
__global__ void k_final(float* __restrict__ out, int nblocks) {
    __shared__ double ssum[64];
    __shared__ int    scnt[64];
    int t = threadIdx.x;    // 64
    double s = 0.0;
    int c = 0;
    for (int b = t; b < nblocks; b += 64) { s += g_blk_sum[b]; c += g_blk_cnt[b]; }
    ssum[t] = s; scnt[t] = c;
    __syncthreads();
    #pragma unroll
    for (int o = 32; o > 0; o >>= 1) {
        if (t < o) { ssum[t] += ssum[t + o]; scnt[t] += scnt[t + o]; }
        __syncthreads();
    }
    if (t == 0) out[0] = (float)(sqrt(ssum[0]) / (double)scnt[0]);
}

// ============================================================
extern "C" void kernel_launch(void* const* d_in, const int* in_sizes, int n_in,
                              void* d_out, int out_size) {
    const float* new_xyz = (const float*)d_in[0];
    const float* xyz     = (const float*)d_in[1];
    const float* gt_sdf  = (const float*)d_in[2];
    int n = in_sizes[2];

    // C = inv(Ci) computed in double (matches reference float64 inverse -> f32 cast)
    CMat C;
    {
        const double EP = 0.21, VP = 0.4;
        double A[3][3] = {{1.0/EP, -VP/EP, -VP/EP},
                          {-VP/EP, 1.0/EP, -VP/EP},
                          {-VP,    -VP,    1.0/EP}};
        double det = A[0][0]*(A[1][1]*A[2][2]-A[1][2]*A[2][1])
                   - A[0][1]*(A[1][0]*A[2][2]-A[1][2]*A[2][0])
                   + A[0][2]*(A[1][0]*A[2][1]-A[1][1]*A[2][0]);
        double inv[3][3];
        inv[0][0] = (A[1][1]*A[2][2]-A[1][2]*A[2][1])/det;
        inv[0][1] = (A[0][2]*A[2][1]-A[0][1]*A[2][2])/det;
        inv[0][2] = (A[0][1]*A[1][2]-A[0][2]*A[1][1])/det;
        inv[1][0] = (A[1][2]*A[2][0]-A[1][0]*A[2][2])/det;
        inv[1][1] = (A[0][0]*A[2][2]-A[0][2]*A[2][0])/det;
        inv[1][2] = (A[0][2]*A[1][0]-A[0][0]*A[1][2])/det;
        inv[2][0] = (A[1][0]*A[2][1]-A[1][1]*A[2][0])/det;
        inv[2][1] = (A[0][1]*A[2][0]-A[0][0]*A[2][1])/det;
        inv[2][2] = (A[0][0]*A[1][1]-A[0][1]*A[1][0])/det;
        for (int i = 0; i < 3; i++)
            for (int j = 0; j < 3; j++)
                C.m[i * 3 + j] = (float)inv[i][j];
        C.s = (float)(EP / (2.0 * (1.0 + VP)));
    }

    k_compact<<<1, 1024>>>(new_xyz, gt_sdf, n);
    dim3 g2((n + QB - 1) / QB, SPLITS);
    k_nn<<<g2, QB>>>();
    int nb3 = (n + 255) / 256;
    k_strain<<<nb3, 256>>>(new_xyz, xyz, C);
    k_final<<<1, 64>>>((float*)d_out, nb3);
}

// round 2
// speedup vs baseline: 1.2142x; 1.2142x over previous
#include <cuda_runtime.h>
#include <math.h>

#define NMAX   12288
#define SEG    1536          // segment length (NMAX / 8)
#define NSEG   8
#define QB     128           // query block size
#define BLKS_PER_SEG (SEG / QB)   // 12

struct CMat { float m[9]; float s; };

// ---- scratch (no allocations allowed) ----
__device__ float4 g_cand[NMAX];                 // segment-compacted inside points {x,y,z,|w|^2}; padded BIG
__device__ int    g_cidx[NMAX];                 // compact slot -> original index
__device__ int    g_cnt[NSEG];                  // per-segment inside count
__device__ float  g_pval[NSEG * NMAX];          // per-split partial min
__device__ int    g_pidx[NSEG * NMAX];          // per-split partial argmin (compact slot)
__device__ double g_blk_sum[64];
__device__ int    g_blk_cnt[64];
__device__ int    g_done = 0;

// ============================================================
// Kernel 1: parallel per-segment compaction (one block per segment)
// ============================================================
__global__ void __launch_bounds__(256) k_compact(const float* __restrict__ new_xyz,
                                                 const float* __restrict__ gt_sdf, int n) {
    __shared__ int s_wsum[8];
    __shared__ int s_base;
    int tid  = threadIdx.x;          // 256
    int lane = tid & 31, wid = tid >> 5;
    int seg  = blockIdx.x;
    int s0   = seg * SEG;
    int s1   = min(s0 + SEG, n);
    if (tid == 0) s_base = 0;
    __syncthreads();

    for (int chunk = s0; chunk < s1; chunk += 256) {
        int idx = chunk + tid;
        bool f = (idx < s1) && (gt_sdf[idx] < 1e-8f);
        unsigned bal = __ballot_sync(0xffffffffu, f);
        int wcnt = __popc(bal);
        int pre  = __popc(bal & ((1u << lane) - 1u));
        if (lane == 0) s_wsum[wid] = wcnt;
        __syncthreads();
        int base = s_base;
        int woff = 0, tot = 0;
        #pragma unroll
        for (int wv = 0; wv < 8; ++wv) {
            int v = s_wsum[wv];
            tot += v;
            if (wv < wid) woff += v;
        }
        if (f) {
            int pos = s0 + base + woff + pre;
            float x = new_xyz[3 * idx + 0];
            float y = new_xyz[3 * idx + 1];
            float z = new_xyz[3 * idx + 2];
            g_cidx[pos] = idx;
            g_cand[pos] = make_float4(x, y, z, x * x + y * y + z * z);
        }
        __syncthreads();
        if (tid == 0) s_base = base + tot;
        __syncthreads();
    }

    int cnt = s_base;
    if (tid == 0) g_cnt[seg] = cnt;
    for (int p = cnt + tid; p < SEG; p += 256)       // pad: safe reads, never wins the min
        g_cand[s0 + p] = make_float4(0.f, 0.f, 0.f, 1e30f);
}

// ============================================================
// Kernel 2: NN search. grid = (NSEG*BLKS_PER_SEG, NSEG)
// d_eff = sq_j - 2 w_i . w_j  (query constant sq_i dropped)
// ============================================================
__global__ void __launch_bounds__(QB) k_nn() {
    __shared__ float4 tile[SEG];
    int qb    = blockIdx.x;
    int csp   = blockIdx.y;
    int qseg  = qb / BLKS_PER_SEG;
    int qb_in = qb % BLKS_PER_SEG;
    int cntq  = g_cnt[qseg];
    if (qb_in * QB >= cntq) return;                  // block-uniform early out
    int cntc  = g_cnt[csp];

    for (int k = threadIdx.x; k < cntc; k += QB)
        tile[k] = g_cand[csp * SEG + k];
    __syncthreads();

    int ql = qb_in * QB + threadIdx.x;
    float4 wq = g_cand[qseg * SEG + min(ql, SEG - 1)];
    float ax = -2.f * wq.x, ay = -2.f * wq.y, az = -2.f * wq.z;
    float best = 3.0e38f;
    int   bc   = 0;

    if (csp != qseg) {
        #pragma unroll 8
        for (int k = 0; k < cntc; ++k) {
            float4 c = tile[k];
            float d = fmaf(c.x, ax, fmaf(c.y, ay, fmaf(c.z, az, c.w)));
            if (d < best) { best = d; bc = k; }
        }
    } else {
        int sk = ql;                                 // self slot within own segment
        #pragma unroll 8
        for (int k = 0; k < cntc; ++k) {
            float4 c = tile[k];
            float d = fmaf(c.x, ax, fmaf(c.y, ay, fmaf(c.z, az, c.w)));
            if (d < best && k != sk) { best = d; bc = k; }
        }
    }

    if (ql < cntq) {
        int qslot = qseg * SEG + ql;
        g_pval[csp * NMAX + qslot] = best;
        g_pidx[csp * NMAX + qslot] = csp * SEG + bc;
    }
}

// ============================================================
// Kernel 3: combine splits + strain + full reduction (last-block)
// ============================================================
__global__ void __launch_bounds__(256) k_strain(const float* __restrict__ xyz,
                                                CMat C, float* __restrict__ out,
                                                int nblocks) {
    __shared__ double s_sum[256];
    __shared__ int    s_cnt[256];
    __shared__ int    s_last;
    int t  = threadIdx.x;
    int qi = blockIdx.x * 256 + t;                   // padded query slot
    int qseg = qi / SEG, ql = qi - qseg * SEG;

    double qsq = 0.0;
    int cnt = 0;
    if (qseg < NSEG && ql < g_cnt[qseg]) {
        float best = 3.5e38f;
        int bc = 0;
        #pragma unroll
        for (int s = 0; s < NSEG; ++s) {             // ascending split: first-occurrence tiebreak
            float v = g_pval[s * NMAX + qi];
            int id  = g_pidx[s * NMAX + qi];
            if (v < best) { best = v; bc = id; }
        }
        float4 wq = g_cand[qi];
        float mind2 = best + wq.w;                   // add back sq_i
        if (mind2 > 1e-16f) {                        // == inside & (nn_d > 1e-8)
            cnt = 1;
            int i  = g_cidx[qi];
            int nn = g_cidx[bc];
            float4 wn = g_cand[bc];
            float xi0 = xyz[3 * i + 0],  xi1 = xyz[3 * i + 1],  xi2 = xyz[3 * i + 2];
            float xn0 = xyz[3 * nn + 0], xn1 = xyz[3 * nn + 1], xn2 = xyz[3 * nn + 2];
            float du = (wn.x - xn0) - (wq.x - xi0);  // dm = motion[nn] - motion[i]
            float dv = (wn.y - xn1) - (wq.y - xi1);
            float dw = (wn.z - xn2) - (wq.z - xi2);
            float dx = wn.x - wq.x + 1e-8f;
            float dy = wn.y - wq.y + 1e-8f;
            float dz = wn.z - wq.z + 1e-8f;
            float e0 = du / dx, e1 = dv / dy, e2 = dw / dz;
            float e3 = (du / dy + dv / dx) * 0.5f;
            float e4 = (du / dz + dw / dx) * 0.5f;
            float e5 = (dw / dy + dv / dz) * 0.5f;
            float r0 = C.m[0] * e0 + C.m[1] * e1 + C.m[2] * e2;
            float r1 = C.m[3] * e0 + C.m[4] * e1 + C.m[5] * e2;
            float r2 = C.m[6] * e0 + C.m[7] * e1 + C.m[8] * e2;
            float q  = e0 * r0 + e1 * r1 + e2 * r2
                     + C.s * (e3 * e3 + e4 * e4 + e5 * e5);
            qsq = (double)q * (double)q;
        }
    }
    s_sum[t] = qsq;
    s_cnt[t] = cnt;
    __syncthreads();
    #pragma unroll
    for (int o = 128; o > 0; o >>= 1) {              // deterministic tree
        if (t < o) { s_sum[t] += s_sum[t + o]; s_cnt[t] += s_cnt[t + o]; }
        __syncthreads();
    }
    if (t == 0) {
        g_blk_sum[blockIdx.x] = s_sum[0];
        g_blk_cnt[blockIdx.x] = s_cnt[0];
        __threadfence();
        int v = atomicAdd(&g_done, 1);
        s_last = (v == nblocks - 1);
    }
    __syncthreads();

    if (s_last) {                                    // last block: fixed-order final reduce
        double s = 0.0; int c = 0;
        if (t < 64) {
            for (int b = t; b < nblocks; b += 64) { s += g_blk_sum[b]; c += g_blk_cnt[b]; }
        }
        s_sum[t] = s; s_cnt[t] = c;
        __syncthreads();
        #pragma unroll
        for (int o = 32; o > 0; o >>= 1) {
            if (t < o) { s_sum[t] += s_sum[t + o]; s_cnt[t] += s_cnt[t + o]; }
            __syncthreads();
        }
        if (t == 0) {
            out[0] = (float)(sqrt(s_sum[0]) / (double)s_cnt[0]);
            g_done = 0;                              // reset for next graph replay
        }
    }
}

// ============================================================
extern "C" void kernel_launch(void* const* d_in, const int* in_sizes, int n_in,
                              void* d_out, int out_size) {
    const float* new_xyz = (const float*)d_in[0];
    const float* xyz     = (const float*)d_in[1];
    const float* gt_sdf  = (const float*)d_in[2];
    int n = in_sizes[2];

    CMat C;
    {
        const double EP = 0.21, VP = 0.4;
        double A[3][3] = {{1.0/EP, -VP/EP, -VP/EP},
                          {-VP/EP, 1.0/EP, -VP/EP},
                          {-VP,    -VP,    1.0/EP}};
        double det = A[0][0]*(A[1][1]*A[2][2]-A[1][2]*A[2][1])
                   - A[0][1]*(A[1][0]*A[2][2]-A[1][2]*A[2][0])
                   + A[0][2]*(A[1][0]*A[2][1]-A[1][1]*A[2][0]);
        double inv[3][3];
        inv[0][0] = (A[1][1]*A[2][2]-A[1][2]*A[2][1])/det;
        inv[0][1] = (A[0][2]*A[2][1]-A[0][1]*A[2][2])/det;
        inv[0][2] = (A[0][1]*A[1][2]-A[0][2]*A[1][1])/det;
        inv[1][0] = (A[1][2]*A[2][0]-A[1][0]*A[2][2])/det;
        inv[1][1] = (A[0][0]*A[2][2]-A[0][2]*A[2][0])/det;
        inv[1][2] = (A[0][2]*A[1][0]-A[0][0]*A[1][2])/det;
        inv[2][0] = (A[1][0]*A[2][1]-A[1][1]*A[2][0])/det;
        inv[2][1] = (A[0][1]*A[2][0]-A[0][0]*A[2][1])/det;
        inv[2][2] = (A[0][0]*A[1][1]-A[0][1]*A[1][0])/det;
        for (int i = 0; i < 3; i++)
            for (int j = 0; j < 3; j++)
                C.m[i * 3 + j] = (float)inv[i][j];
        C.s = (float)(EP / (2.0 * (1.0 + VP)));
    }

    k_compact<<<NSEG, 256>>>(new_xyz, gt_sdf, n);
    dim3 g2(NSEG * BLKS_PER_SEG, NSEG);
    k_nn<<<g2, QB>>>();
    int nb3 = (NMAX + 255) / 256;                    // 48 blocks over padded slots
    k_strain<<<nb3, 256>>>(xyz, C, (float*)d_out, nb3);
}